// round 17
// baseline (speedup 1.0000x reference)
#include <cuda_runtime.h>
#include <math.h>
#include <stdint.h>

#define BWIN   2048
#define NTOK   64
#define CDIM   256
#define MROWS  (BWIN * NTOK)
#define NBATCH 32
#define SCALE  0.0625f

// ---------------- scratch ----------------------------------------------------
__device__ float g_bias[NBATCH * NTOK * NTOK];
__device__ float g_Wc[512 * CDIM];    // tf32 bits: rows 0-255 = M, 256-511 = Wz
__device__ float g_wv[CDIM];
__device__ float g_d [CDIM];
__device__ float g_Z [MROWS * CDIM];  // tf32

// ---------------- helpers -----------------------------------------------------
__device__ __forceinline__ uint32_t f2tf(float f) {
    uint32_t u; asm("cvt.rna.tf32.f32 %0, %1;" : "=r"(u) : "f"(f)); return u;
}
__device__ __forceinline__ uint32_t u2tf(uint32_t x) {
    uint32_t u; asm("cvt.rna.tf32.f32 %0, %1;" : "=r"(u) : "f"(__uint_as_float(x))); return u;
}
__device__ __forceinline__ void mma8(float* c, uint32_t a0, uint32_t a1, uint32_t a2, uint32_t a3,
                                     uint32_t b0, uint32_t b1) {
    asm volatile(
        "mma.sync.aligned.m16n8k8.row.col.f32.tf32.tf32.f32 "
        "{%0,%1,%2,%3},{%4,%5,%6,%7},{%8,%9},{%0,%1,%2,%3};"
        : "+f"(c[0]), "+f"(c[1]), "+f"(c[2]), "+f"(c[3])
        : "r"(a0), "r"(a1), "r"(a2), "r"(a3), "r"(b0), "r"(b1));
}
__device__ __forceinline__ void ldsm4(uint32_t* r, const uint32_t* p) {
    uint32_t a = (uint32_t)__cvta_generic_to_shared(p);
    asm volatile("ldmatrix.sync.aligned.m8n8.x4.shared.b16 {%0,%1,%2,%3}, [%4];"
                 : "=r"(r[0]), "=r"(r[1]), "=r"(r[2]), "=r"(r[3]) : "r"(a));
}
__device__ __forceinline__ void cpasync16(uint32_t dst, const void* src) {
    asm volatile("cp.async.ca.shared.global [%0], [%1], 16;" :: "r"(dst), "l"(src));
}
__device__ __forceinline__ void cp_commit() { asm volatile("cp.async.commit_group;"); }
template <int N> __device__ __forceinline__ void cp_wait() {
    asm volatile("cp.async.wait_group %0;" :: "n"(N));
}

// ---------------- bias precompute ---------------------------------------------
__global__ void bias_kernel(const float* __restrict__ theta_max,
                            const float* __restrict__ a_p, const float* __restrict__ b_p,
                            const float* __restrict__ a_r, const float* __restrict__ b_r,
                            const int*   __restrict__ radius,
                            const int*   __restrict__ azimuth)
{
    const int b = blockIdx.x >> 4;
    const int i = (blockIdx.x & 15) * 256 + threadIdx.x;
    const float tm = theta_max[b];
    const float azc = 2.0f * 3.14159265358979323846f / 64.0f;
    int az = azimuth[i];
    int ai = az < 0 ? az + 15 : az;
    float azf = (float)az * azc;
    float phi = a_p[ai] * cosf(azf) + b_p[ai] * sinf(azf);
    int r = radius[i];
    int ri = r < 0 ? r + 15 : r;
    float rn = (float)r * tm * (1.0f / 64.0f);
    float th = a_r[ri] * cosf(rn) + b_r[ri] * sinf(rn);
    g_bias[b * (NTOK * NTOK) + i] = phi + th;
}

// ---------------- weight-product precompute (blocked) ---------------------------
__global__ __launch_bounds__(256)
void mat_kernel(const float* __restrict__ qkv_w, const float* __restrict__ qkv_b,
                const float* __restrict__ proj_w, const float* __restrict__ proj_b)
{
    __shared__ float pane[4][256];
    const int b = blockIdx.x, c = threadIdx.x;
    if (b < 64) {                        // M rows e0..e0+3
        const int e0 = b * 4;
        for (int t = 0; t < 4; t++) {
            int idx = c + t * 256;
            int i = idx >> 2, j = idx & 3;
            pane[j][i] = qkv_w[(256 + i) * 256 + e0 + j];
        }
        __syncthreads();
        float acc[4] = {};
        for (int i = 0; i < 256; i++) {
            float wq = qkv_w[i * 256 + c];
            acc[0] += wq * pane[0][i];
            acc[1] += wq * pane[1][i];
            acc[2] += wq * pane[2][i];
            acc[3] += wq * pane[3][i];
        }
#pragma unroll
        for (int j = 0; j < 4; j++)
            g_Wc[(e0 + j) * 256 + c] = __uint_as_float(f2tf(acc[j] * SCALE));
    } else if (b < 128) {                // Wz rows j0..j0+3
        const int j0 = (b - 64) * 4;
        for (int t = 0; t < 4; t++) {
            int idx = c + t * 256;
            int j = idx >> 8, i = idx & 255;
            pane[j][i] = proj_w[(j0 + j) * 256 + i];
        }
        __syncthreads();
        float acc[4] = {};
        for (int i = 0; i < 256; i++) {
            float wv = qkv_w[(512 + i) * 256 + c];
            acc[0] += pane[0][i] * wv;
            acc[1] += pane[1][i] * wv;
            acc[2] += pane[2][i] * wv;
            acc[3] += pane[3][i] * wv;
        }
#pragma unroll
        for (int j = 0; j < 4; j++)
            g_Wc[(256 + j0 + j) * 256 + c] = __uint_as_float(f2tf(acc[j]));
    } else if (b == 128) {
        float s = 0.f;
        for (int i = 0; i < 256; i++)
            s += qkv_w[(256 + i) * 256 + c] * qkv_b[i];
        g_wv[c] = s;
    } else {
        float s = proj_b[c];
        for (int i = 0; i < 256; i++)
            s += proj_w[c * 256 + i] * qkv_b[512 + i];
        g_d[c] = s;
    }
}

// ---------------- Kernel A: Z = X @ Wz^T, 3-stage / single-sync -----------------
// BM=128, BN=256, BK=32, 256 threads, 8 warps (2M x 4N), warp tile 64x64.
#define AS_STRIDE 36
#define ASTG (128 * AS_STRIDE)
#define WSTG (256 * AS_STRIDE)
#define GEMM_SMEM_WORDS (3 * (ASTG + WSTG))

__global__ __launch_bounds__(256)
void gemm_z_kernel(const float* __restrict__ A)
{
    extern __shared__ uint32_t smem[];
    uint32_t* As = smem;
    uint32_t* Ws = smem + 3 * ASTG;
    const float* W = g_Wc + 256 * 256;   // Wz half

    const int tid = threadIdx.x, lane = tid & 31, wid = tid >> 5;
    const int g = lane >> 2, tg = lane & 3;
    const int wm0 = (wid & 1) * 64, wn0 = (wid >> 1) * 64;
    const int m0 = blockIdx.y << 7;

    const int lrA = (lane & 7) + ((lane >> 3) & 1) * 8;
    const int lkA = ((lane >> 4) & 1) * 4;
    const int lrB = (lane & 7) + ((lane >> 4) & 1) * 8;
    const int lkB = ((lane >> 3) & 1) * 4;

    const uint32_t sA = (uint32_t)__cvta_generic_to_shared(As);
    const uint32_t sW = (uint32_t)__cvta_generic_to_shared(Ws);

    uint32_t dA[4]; size_t gA[4];
#pragma unroll
    for (int i = 0; i < 4; i++) {
        int lin = tid + (i << 8); int r = lin >> 3, c = (lin & 7) << 2;
        dA[i] = (uint32_t)(r * AS_STRIDE + c) * 4;
        gA[i] = (size_t)(m0 + r) * 256 + c;
    }
    uint32_t dW[8]; size_t gW[8];
#pragma unroll
    for (int i = 0; i < 8; i++) {
        int lin = tid + (i << 8); int r = lin >> 3, c = (lin & 7) << 2;
        dW[i] = (uint32_t)(r * AS_STRIDE + c) * 4;
        gW[i] = (size_t)r * 256 + c;
    }

    float acc[4][8][4] = {};

#define ISSUE(s, k0)                                                    \
    do {                                                                \
        const int _k0 = (k0);                                           \
        uint32_t obA = (uint32_t)(s) * (ASTG * 4);                      \
        uint32_t obW = (uint32_t)(s) * (WSTG * 4);                      \
        _Pragma("unroll")                                               \
        for (int _ci = 0; _ci < 4; _ci++)                               \
            cpasync16(sA + obA + dA[_ci], A + gA[_ci] + _k0);           \
        _Pragma("unroll")                                               \
        for (int _ci = 0; _ci < 8; _ci++)                               \
            cpasync16(sW + obW + dW[_ci], W + gW[_ci] + _k0);           \
        cp_commit();                                                    \
    } while (0)

    ISSUE(0, 0);
    ISSUE(1, 32);

#pragma unroll
    for (int it = 0; it < 8; it++) {
        const int s = it % 3;
        if (it == 7) cp_wait<0>(); else cp_wait<1>();
        __syncthreads();

        const uint32_t* Ab = As + s * ASTG;
        const uint32_t* Wb = Ws + s * WSTG;
#pragma unroll
        for (int ks = 0; ks < 32; ks += 8) {
            uint32_t a[4][4], b[4][4];
#pragma unroll
            for (int mt = 0; mt < 4; mt++)
                ldsm4(a[mt], &Ab[(wm0 + mt * 16 + lrA) * AS_STRIDE + ks + lkA]);
#pragma unroll
            for (int p = 0; p < 4; p++)
                ldsm4(b[p], &Wb[(wn0 + p * 16 + lrB) * AS_STRIDE + ks + lkB]);
#pragma unroll
            for (int mt = 0; mt < 4; mt++)
#pragma unroll
                for (int j = 0; j < 4; j++) a[mt][j] = u2tf(a[mt][j]);
#pragma unroll
            for (int mt = 0; mt < 4; mt++)
#pragma unroll
                for (int nt = 0; nt < 8; nt++) {
                    int p = nt >> 1, hi = (nt & 1) * 2;
                    mma8(acc[mt][nt], a[mt][0], a[mt][1], a[mt][2], a[mt][3], b[p][hi], b[p][hi + 1]);
                }
        }
        if (it + 2 < 8) ISSUE((it + 2) % 3, (it + 2) * 32);
    }
#undef ISSUE

#pragma unroll
    for (int mt = 0; mt < 4; mt++)
#pragma unroll
        for (int nt = 0; nt < 8; nt++) {
            int coln = wn0 + nt * 8 + 2 * tg;
            int r = m0 + wm0 + mt * 16 + g;
            uint2 v0 = { f2tf(acc[mt][nt][0]), f2tf(acc[mt][nt][1]) };
            uint2 v1 = { f2tf(acc[mt][nt][2]), f2tf(acc[mt][nt][3]) };
            *(uint2*)(g_Z + (size_t)r * 256 + coln)       = v0;
            *(uint2*)(g_Z + (size_t)(r + 8) * 256 + coln) = v1;
        }
}

// ---------------- fused attention: G1 in smem, no HBM round-trip ----------------
// 512 threads, 16 warps. Phases:
//  (0) X -> Xs (tf32, resident); a2 from Xs.
//  (1) G1 = Xs @ M^T   (M streamed 3-stage from L2; warps 2M x 8E, tile 32x32)
//  (2) S = G1 @ Xs^T + bias + a2  (warps 4M x 4N, tile 16x16)
//  (3) softmax -> P (tf32 in Ss)
//  (4) out = P @ Z + d  (Z direct from global; warps 2M x 8N, tile 32x32)
#define XS_STRIDE 260
#define GS_STRIDE 260
#define MS_STRIDE 36
#define MSTG (256 * MS_STRIDE)               // 9216 words per stage
#define SS_STRIDE 68
#define OFF_XS  0
#define OFF_MST (64 * XS_STRIDE)             // 16640 (also Gs after G1 phase)
#define OFF_SS  (OFF_MST + 3 * MSTG)         // 44288
#define OFF_WV  (OFF_SS + 64 * SS_STRIDE)    // 48640
#define OFF_A2S (OFF_WV + 256)               // 48896
#define FUSED_SMEM_WORDS (OFF_A2S + 64)      // 48960 words = 195840 B

__global__ __launch_bounds__(512)
void attn_fused_kernel(const float* __restrict__ x, float* __restrict__ out)
{
    extern __shared__ uint32_t sm[];
    uint32_t* Xs  = sm + OFF_XS;
    uint32_t* Mst = sm + OFF_MST;
    uint32_t* Gs  = sm + OFF_MST;            // alias: reused after G1 phase
    uint32_t* Ss  = sm + OFF_SS;
    float*    wvs = (float*)(sm + OFF_WV);
    float*    a2s = (float*)(sm + OFF_A2S);

    const int tid = threadIdx.x, lane = tid & 31, wid = tid >> 5;
    const int g = lane >> 2, tg = lane & 3;
    const int w = blockIdx.x;
    const size_t base = (size_t)w * NTOK * CDIM;

    const int lrA = (lane & 7) + ((lane >> 3) & 1) * 8;
    const int lkA = ((lane >> 4) & 1) * 4;
    const int lrB = (lane & 7) + ((lane >> 4) & 1) * 8;
    const int lkB = ((lane >> 3) & 1) * 4;

    if (tid < 256) wvs[tid] = g_wv[tid];

    const uint32_t sM = (uint32_t)__cvta_generic_to_shared(Mst);
    // M staging: 2048 16B-chunks per stage, 4 per thread
    uint32_t dM[4]; size_t gM[4];
#pragma unroll
    for (int i = 0; i < 4; i++) {
        int lin = tid + (i << 9); int r = lin >> 3, c = (lin & 7) << 2;
        dM[i] = (uint32_t)(r * MS_STRIDE + c) * 4;
        gM[i] = (size_t)r * 256 + c;
    }

#define ISSUE_M(s, k0)                                                   \
    do {                                                                 \
        const int _k0 = (k0);                                            \
        uint32_t _ob = (uint32_t)(s) * (MSTG * 4);                       \
        _Pragma("unroll")                                                \
        for (int _ci = 0; _ci < 4; _ci++)                                \
            cpasync16(sM + _ob + dM[_ci], g_Wc + gM[_ci] + _k0);         \
        cp_commit();                                                     \
    } while (0)

    ISSUE_M(0, 0);
    ISSUE_M(1, 32);

    // X -> Xs (tf32)
#pragma unroll
    for (int i = 0; i < 8; i++) {
        int lin = tid + (i << 9); int r = lin >> 6, c = (lin & 63) << 2;
        float4 v = *(const float4*)(x + base + r * 256 + c);
        uint4 u; u.x = f2tf(v.x); u.y = f2tf(v.y); u.z = f2tf(v.z); u.w = f2tf(v.w);
        *(uint4*)&Xs[r * XS_STRIDE + c] = u;
    }
    __syncthreads();

    // a2[m] = SCALE * x[m,:]·wv from tf32 Xs (8 threads/row, 32 cols each)
    {
        int r = tid >> 3, p = tid & 7;
        float s = 0.f;
#pragma unroll 8
        for (int j = 0; j < 32; j++) {
            int c = p * 32 + j;
            s += __uint_as_float(Xs[r * XS_STRIDE + c]) * wvs[c];
        }
        s += __shfl_xor_sync(0xffffffffu, s, 1);
        s += __shfl_xor_sync(0xffffffffu, s, 2);
        s += __shfl_xor_sync(0xffffffffu, s, 4);
        if (p == 0) a2s[r] = s * SCALE;
    }

    // ---- phase 1: G1 = Xs @ M^T  (64 x 256, k=256), warps 2M x 8E ----
    {
        const int wm0 = (wid & 1) * 32, we0 = (wid >> 1) * 32;
        float acc[2][4][4] = {};
#pragma unroll
        for (int it = 0; it < 8; it++) {
            const int s = it % 3;
            if (it == 7) cp_wait<0>(); else cp_wait<1>();
            __syncthreads();

            const uint32_t* Mb = Mst + s * MSTG;
#pragma unroll
            for (int ks = 0; ks < 32; ks += 8) {
                const int kk = it * 32 + ks;          // Xs k advances with it
                uint32_t a[2][4], b[2][4];
#pragma unroll
                for (int mt = 0; mt < 2; mt++)
                    ldsm4(a[mt], &Xs[(wm0 + mt * 16 + lrA) * XS_STRIDE + kk + lkA]);
#pragma unroll
                for (int p = 0; p < 2; p++)
                    ldsm4(b[p], &Mb[(we0 + p * 16 + lrB) * MS_STRIDE + ks + lkB]);
#pragma unroll
                for (int mt = 0; mt < 2; mt++)
#pragma unroll
                    for (int nt = 0; nt < 4; nt++) {
                        int p = nt >> 1, hi = (nt & 1) * 2;
                        mma8(acc[mt][nt], a[mt][0], a[mt][1], a[mt][2], a[mt][3], b[p][hi], b[p][hi + 1]);
                    }
            }
            if (it + 2 < 8) ISSUE_M((it + 2) % 3, (it + 2) * 32);
        }
        __syncthreads();   // all warps done reading Mst before Gs overwrite

        // G1 -> Gs (tf32, stride 260)
#pragma unroll
        for (int mt = 0; mt < 2; mt++)
#pragma unroll
            for (int nt = 0; nt < 4; nt++) {
                int col = we0 + nt * 8 + 2 * tg;
                int r = wm0 + mt * 16 + g;
                uint2 v0 = { f2tf(acc[mt][nt][0]), f2tf(acc[mt][nt][1]) };
                uint2 v1 = { f2tf(acc[mt][nt][2]), f2tf(acc[mt][nt][3]) };
                *(uint2*)&Gs[r * GS_STRIDE + col]       = v0;
                *(uint2*)&Gs[(r + 8) * GS_STRIDE + col] = v1;
            }
    }
    __syncthreads();
#undef ISSUE_M

    // ---- phase 2: S = G1 @ Xs^T  (64 x 64, k=256), warps 4M x 4N, tile 16x16 ----
    {
        const int wm1 = (wid & 3) * 16, wn1 = (wid >> 2) * 16;
        float acc1[2][4] = {};
#pragma unroll 4
        for (int ks = 0; ks < 256; ks += 8) {
            uint32_t a[4], b[4];
            ldsm4(a, &Gs[(wm1 + lrA) * GS_STRIDE + ks + lkA]);
            ldsm4(b, &Xs[(wn1 + lrB) * XS_STRIDE + ks + lkB]);
            mma8(acc1[0], a[0], a[1], a[2], a[3], b[0], b[1]);
            mma8(acc1[1], a[0], a[1], a[2], a[3], b[2], b[3]);
        }
        const float* bb = g_bias + (w >> 6) * (NTOK * NTOK);
        float* Sf = (float*)Ss;
#pragma unroll
        for (int nt = 0; nt < 2; nt++) {
            int col = wn1 + nt * 8 + 2 * tg;
            int r0 = wm1 + g;
            float a0 = a2s[col], a1 = a2s[col + 1];
            Sf[r0 * SS_STRIDE + col]           = acc1[nt][0] + bb[r0 * 64 + col]       + a0;
            Sf[r0 * SS_STRIDE + col + 1]       = acc1[nt][1] + bb[r0 * 64 + col + 1]   + a1;
            Sf[(r0 + 8) * SS_STRIDE + col]     = acc1[nt][2] + bb[(r0 + 8) * 64 + col] + a0;
            Sf[(r0 + 8) * SS_STRIDE + col + 1] = acc1[nt][3] + bb[(r0 + 8) * 64 + col + 1] + a1;
        }
    }
    __syncthreads();

    // ---- phase 3: softmax over keys (8 threads/row); P as tf32 ----
    {
        float* Sf = (float*)Ss;
        int r = tid >> 3, p = tid & 7;
        float v[8];
        float mx = -1e30f;
#pragma unroll
        for (int i = 0; i < 8; i++) { v[i] = Sf[r * SS_STRIDE + p + 8 * i]; mx = fmaxf(mx, v[i]); }
        mx = fmaxf(mx, __shfl_xor_sync(0xffffffffu, mx, 1));
        mx = fmaxf(mx, __shfl_xor_sync(0xffffffffu, mx, 2));
        mx = fmaxf(mx, __shfl_xor_sync(0xffffffffu, mx, 4));
        float s = 0.f;
#pragma unroll
        for (int i = 0; i < 8; i++) { v[i] = __expf(v[i] - mx); s += v[i]; }
        s += __shfl_xor_sync(0xffffffffu, s, 1);
        s += __shfl_xor_sync(0xffffffffu, s, 2);
        s += __shfl_xor_sync(0xffffffffu, s, 4);
        float inv = 1.0f / s;
#pragma unroll
        for (int i = 0; i < 8; i++) Ss[r * SS_STRIDE + p + 8 * i] = f2tf(v[i] * inv);
    }
    __syncthreads();

    // ---- phase 4: out = P @ Z + d  (64 x 256, k=64), warps 2M x 8N ----
    {
        const int wm2 = (wid & 1) * 32, wn2 = (wid >> 1) * 32;
        const uint32_t* Zp = (const uint32_t*)g_Z + base;
        float acc2[2][4][4] = {};
#pragma unroll
        for (int ks = 0; ks < 64; ks += 8) {
            uint32_t a[2][4];
#pragma unroll
            for (int mt = 0; mt < 2; mt++)
                ldsm4(a[mt], &Ss[(wm2 + mt * 16 + lrA) * SS_STRIDE + ks + lkA]);
            uint32_t b0[4], b1[4];
#pragma unroll
            for (int nt = 0; nt < 4; nt++) {
                b0[nt] = Zp[(ks + tg) * 256 + wn2 + nt * 8 + g];
                b1[nt] = Zp[(ks + tg + 4) * 256 + wn2 + nt * 8 + g];
            }
#pragma unroll
            for (int nt = 0; nt < 4; nt++)
#pragma unroll
                for (int mt = 0; mt < 2; mt++)
                    mma8(acc2[mt][nt], a[mt][0], a[mt][1], a[mt][2], a[mt][3], b0[nt], b1[nt]);
        }
#pragma unroll
        for (int mt = 0; mt < 2; mt++)
#pragma unroll
            for (int nt = 0; nt < 4; nt++) {
                int col = wn2 + nt * 8 + 2 * tg, r0 = wm2 + mt * 16 + g;
                float d0 = g_d[col], d1 = g_d[col + 1];
                float2 v0 = { acc2[mt][nt][0] + d0, acc2[mt][nt][1] + d1 };
                float2 v1 = { acc2[mt][nt][2] + d0, acc2[mt][nt][3] + d1 };
                *(float2*)(out + base + r0 * 256 + col)       = v0;
                *(float2*)(out + base + (r0 + 8) * 256 + col) = v1;
            }
    }
}

// ---------------- launch --------------------------------------------------------
extern "C" void kernel_launch(void* const* d_in, const int* in_sizes, int n_in,
                              void* d_out, int out_size)
{
    const float* x         = (const float*)d_in[0];
    const float* theta_max = (const float*)d_in[1];
    const float* qkv_w     = (const float*)d_in[2];
    const float* qkv_b     = (const float*)d_in[3];
    const float* proj_w    = (const float*)d_in[4];
    const float* proj_b    = (const float*)d_in[5];
    const float* a_p       = (const float*)d_in[6];
    const float* b_p       = (const float*)d_in[7];
    const float* a_r       = (const float*)d_in[8];
    const float* b_r       = (const float*)d_in[9];
    const int*   radius    = (const int*)d_in[10];
    const int*   azimuth   = (const int*)d_in[11];
    float*       out       = (float*)d_out;

    bias_kernel<<<NBATCH * 16, 256>>>(theta_max, a_p, b_p, a_r, b_r, radius, azimuth);
    mat_kernel<<<130, 256>>>(qkv_w, qkv_b, proj_w, proj_b);

    const int gemm_smem = GEMM_SMEM_WORDS * (int)sizeof(uint32_t);
    cudaFuncSetAttribute(gemm_z_kernel, cudaFuncAttributeMaxDynamicSharedMemorySize, gemm_smem);
    gemm_z_kernel<<<dim3(1, MROWS / 128), 256, gemm_smem>>>(x);

    const int fused_smem = FUSED_SMEM_WORDS * (int)sizeof(uint32_t);
    cudaFuncSetAttribute(attn_fused_kernel, cudaFuncAttributeMaxDynamicSharedMemorySize, fused_smem);
    attn_fused_kernel<<<BWIN, 512, fused_smem>>>(x, out);
}